// round 1
// baseline (speedup 1.0000x reference)
#include <cuda_runtime.h>
#include <math.h>
#include <stdint.h>

// Problem dims (fixed by the dataset)
#define BSZ   8
#define LSEQ  4096
#define HDIM  1024
#define PDIM  512
#define MTOT  (BSZ * LSEQ)      // 32768
#define KDIM  1024              // contraction dim for both GEMMs (H, then 2P)

// ---------------- scratch (device globals; no allocations allowed) ----------
__device__ float g_lb [2 * PDIM];           // Lambda_bar re | im
__device__ float g_fac[2 * PDIM];           // (Lambda_bar-1)/Lambda re | im
__device__ float g_W1 [KDIM * KDIM];        // (1024 x 1024): rows 0..511 = Re(B_bar), 512..1023 = Im(B_bar)
__device__ float g_W2 [KDIM * KDIM];        // (1024 x 1024): [C_re | -C_im] per H row
__device__ float g_Bu [(size_t)MTOT * KDIM]; // (M, 1024): cols 0..511 re, 512..1023 im
__device__ float g_xs [(size_t)MTOT * KDIM]; // same layout

// ---------------- param prep ------------------------------------------------
__global__ void prep_lambda_kernel(const float* __restrict__ Lre,
                                   const float* __restrict__ Lim,
                                   const float* __restrict__ lstep)
{
    int p = blockIdx.x * blockDim.x + threadIdx.x;
    if (p >= PDIM) return;
    double lr = fmin((double)Lre[p], -1e-4);
    double li = (double)Lim[p];
    double s  = exp((double)lstep[p]);
    double er = exp(lr * s);
    double th = li * s;
    double lbre = er * cos(th);
    double lbim = er * sin(th);
    double den = lr * lr + li * li;
    double gre = lbre - 1.0;
    double gim = lbim;
    g_lb[p]          = (float)lbre;
    g_lb[PDIM + p]   = (float)lbim;
    g_fac[p]         = (float)((gre * lr + gim * li) / den);
    g_fac[PDIM + p]  = (float)((gim * lr - gre * li) / den);
}

__global__ void prep_w1_kernel(const float* __restrict__ Bp) // (P, H, 2)
{
    int idx = blockIdx.x * blockDim.x + threadIdx.x;
    if (idx >= PDIM * HDIM) return;
    int p = idx >> 10;
    int h = idx & 1023;
    float b0 = Bp[p * 2048 + h * 2 + 0];
    float b1 = Bp[p * 2048 + h * 2 + 1];
    float fr = g_fac[p];
    float fi = g_fac[PDIM + p];
    g_W1[(size_t)p * KDIM + h]          = fr * b0 - fi * b1;  // Re(B_bar)
    g_W1[(size_t)(PDIM + p) * KDIM + h] = fr * b1 + fi * b0;  // Im(B_bar)
}

__global__ void prep_w2_kernel(const float* __restrict__ Cp) // (H, P, 2)
{
    int idx = blockIdx.x * blockDim.x + threadIdx.x;
    if (idx >= HDIM * PDIM) return;
    int h = idx >> 9;
    int p = idx & 511;
    g_W2[(size_t)h * KDIM + p]        =  Cp[h * 1024 + p * 2 + 0];
    g_W2[(size_t)h * KDIM + PDIM + p] = -Cp[h * 1024 + p * 2 + 1];
}

// ---------------- SGEMM: C = A(MxK) * B(NxK)^T  [+ D*U epilogue] ------------
// 128x128 block tile, BK=16, 8x8 per thread, 256 threads, double-buffered smem.
template<bool EPI>
__global__ __launch_bounds__(256, 2)
void sgemm_tn(const float* __restrict__ A, const float* __restrict__ Bm,
              float* __restrict__ Cout,
              const float* __restrict__ Dv, const float* __restrict__ U,
              int M, int N, int K)
{
    __shared__ float As[2][16][128];
    __shared__ float Bs[2][16][128];

    const int bm = blockIdx.y * 128;
    const int bn = blockIdx.x * 128;
    const int tid = threadIdx.x;
    const int tx = tid & 15;    // n-direction (8 cols each)
    const int ty = tid >> 4;    // m-direction (8 rows each)

    const int lr = tid >> 2;          // 0..63 : tile row for loads
    const int lc = (tid & 3) * 4;     // 0,4,8,12 : k offset for float4 load

    const float* Aptr = A  + (size_t)(bm + lr) * K + lc;
    const float* Bptr = Bm + (size_t)(bn + lr) * K + lc;

    float4 ra0, ra1, rb0, rb1;
    float acc[8][8];
    #pragma unroll
    for (int i = 0; i < 8; i++)
        #pragma unroll
        for (int j = 0; j < 8; j++) acc[i][j] = 0.0f;

    // prologue: global -> regs tile 0
    ra0 = *(const float4*)(Aptr);
    ra1 = *(const float4*)(Aptr + (size_t)64 * K);
    rb0 = *(const float4*)(Bptr);
    rb1 = *(const float4*)(Bptr + (size_t)64 * K);

    // regs -> shared buf 0 (transposed)
    {
        As[0][lc+0][lr] = ra0.x; As[0][lc+1][lr] = ra0.y; As[0][lc+2][lr] = ra0.z; As[0][lc+3][lr] = ra0.w;
        As[0][lc+0][lr+64] = ra1.x; As[0][lc+1][lr+64] = ra1.y; As[0][lc+2][lr+64] = ra1.z; As[0][lc+3][lr+64] = ra1.w;
        Bs[0][lc+0][lr] = rb0.x; Bs[0][lc+1][lr] = rb0.y; Bs[0][lc+2][lr] = rb0.z; Bs[0][lc+3][lr] = rb0.w;
        Bs[0][lc+0][lr+64] = rb1.x; Bs[0][lc+1][lr+64] = rb1.y; Bs[0][lc+2][lr+64] = rb1.z; Bs[0][lc+3][lr+64] = rb1.w;
    }
    __syncthreads();

    const int NT = K >> 4;
    for (int kt = 0; kt < NT; kt++) {
        if (kt + 1 < NT) {
            const float* Ap = Aptr + (kt + 1) * 16;
            const float* Bp = Bptr + (kt + 1) * 16;
            ra0 = *(const float4*)(Ap);
            ra1 = *(const float4*)(Ap + (size_t)64 * K);
            rb0 = *(const float4*)(Bp);
            rb1 = *(const float4*)(Bp + (size_t)64 * K);
        }
        const int cb = kt & 1;
        #pragma unroll
        for (int k = 0; k < 16; k++) {
            float a[8], b[8];
            *(float4*)(a)     = *(const float4*)&As[cb][k][ty * 8];
            *(float4*)(a + 4) = *(const float4*)&As[cb][k][ty * 8 + 4];
            *(float4*)(b)     = *(const float4*)&Bs[cb][k][tx * 8];
            *(float4*)(b + 4) = *(const float4*)&Bs[cb][k][tx * 8 + 4];
            #pragma unroll
            for (int i = 0; i < 8; i++)
                #pragma unroll
                for (int j = 0; j < 8; j++)
                    acc[i][j] = fmaf(a[i], b[j], acc[i][j]);
        }
        if (kt + 1 < NT) {
            const int nb = (kt + 1) & 1;
            As[nb][lc+0][lr] = ra0.x; As[nb][lc+1][lr] = ra0.y; As[nb][lc+2][lr] = ra0.z; As[nb][lc+3][lr] = ra0.w;
            As[nb][lc+0][lr+64] = ra1.x; As[nb][lc+1][lr+64] = ra1.y; As[nb][lc+2][lr+64] = ra1.z; As[nb][lc+3][lr+64] = ra1.w;
            Bs[nb][lc+0][lr] = rb0.x; Bs[nb][lc+1][lr] = rb0.y; Bs[nb][lc+2][lr] = rb0.z; Bs[nb][lc+3][lr] = rb0.w;
            Bs[nb][lc+0][lr+64] = rb1.x; Bs[nb][lc+1][lr+64] = rb1.y; Bs[nb][lc+2][lr+64] = rb1.z; Bs[nb][lc+3][lr+64] = rb1.w;
            __syncthreads();
        }
    }

    // epilogue
    float dreg[8];
    if (EPI) {
        #pragma unroll
        for (int j = 0; j < 8; j++) dreg[j] = Dv[bn + tx * 8 + j];
    }
    #pragma unroll
    for (int i = 0; i < 8; i++) {
        const int m = bm + ty * 8 + i;
        float* crow = Cout + (size_t)m * N + bn + tx * 8;
        if (EPI) {
            const float* urow = U + (size_t)m * N + bn + tx * 8;
            #pragma unroll
            for (int j = 0; j < 8; j++) acc[i][j] = fmaf(dreg[j], urow[j], acc[i][j]);
        }
        *(float4*)(crow)     = make_float4(acc[i][0], acc[i][1], acc[i][2], acc[i][3]);
        *(float4*)(crow + 4) = make_float4(acc[i][4], acc[i][5], acc[i][6], acc[i][7]);
    }
}

// ---------------- complex linear recurrence over L ---------------------------
// One thread per (batch, p): x_k = lambda_bar * x_{k-1} + Bu_k
__global__ void scan_kernel()
{
    int idx = blockIdx.x * blockDim.x + threadIdx.x;  // 0..4095
    if (idx >= BSZ * PDIM) return;
    int b = idx >> 9;        // /512
    int p = idx & 511;
    const float lre = g_lb[p];
    const float lim = g_lb[PDIM + p];
    const float* __restrict__ bu = g_Bu + (size_t)b * LSEQ * KDIM;
    float* __restrict__ xs = g_xs + (size_t)b * LSEQ * KDIM;

    float xr = 0.0f, xi = 0.0f;
    #pragma unroll 8
    for (int l = 0; l < LSEQ; l++) {
        const size_t base = (size_t)l * KDIM;
        float br = bu[base + p];
        float bi = bu[base + PDIM + p];
        float nr = fmaf(lre, xr, fmaf(-lim, xi, br));
        float ni = fmaf(lre, xi, fmaf( lim, xr, bi));
        xr = nr; xi = ni;
        xs[base + p]        = xr;
        xs[base + PDIM + p] = xi;
    }
}

// ---------------- launcher ----------------------------------------------------
extern "C" void kernel_launch(void* const* d_in, const int* in_sizes, int n_in,
                              void* d_out, int out_size)
{
    const float* u     = (const float*)d_in[0];
    const float* Lre   = (const float*)d_in[1];
    const float* Lim   = (const float*)d_in[2];
    const float* Bp    = (const float*)d_in[3];
    const float* Cp    = (const float*)d_in[4];
    const float* Dv    = (const float*)d_in[5];
    const float* lstep = (const float*)d_in[6];
    float* out = (float*)d_out;

    void *pW1, *pW2, *pBu, *pxs;
    cudaGetSymbolAddress(&pW1, g_W1);
    cudaGetSymbolAddress(&pW2, g_W2);
    cudaGetSymbolAddress(&pBu, g_Bu);
    cudaGetSymbolAddress(&pxs, g_xs);

    prep_lambda_kernel<<<2, 256>>>(Lre, Lim, lstep);
    prep_w1_kernel<<<(PDIM * HDIM) / 256, 256>>>(Bp);
    prep_w2_kernel<<<(HDIM * PDIM) / 256, 256>>>(Cp);

    dim3 grid(KDIM / 128, MTOT / 128);  // (8, 256)
    // GEMM1: Bu = u @ W1^T
    sgemm_tn<false><<<grid, 256>>>(u, (const float*)pW1, (float*)pBu,
                                   nullptr, nullptr, MTOT, KDIM, HDIM);
    // scan over L
    scan_kernel<<<(BSZ * PDIM) / 256, 256>>>();
    // GEMM2: ys = xs @ W2^T + D*u
    sgemm_tn<true><<<grid, 256>>>((const float*)pxs, (const float*)pW2, out,
                                  Dv, u, MTOT, KDIM, KDIM);
}

// round 3
// speedup vs baseline: 3.1504x; 3.1504x over previous
#include <cuda_runtime.h>
#include <cuda_bf16.h>
#include <math.h>
#include <stdint.h>

// ---------------- problem dims (fixed) ----------------
#define BSZ   8
#define LSEQ  4096
#define HDIM  1024
#define PDIM  512
#define MTOT  (BSZ * LSEQ)        // 32768
#define KSPL  2048                // hi|lo split width
#define CHUNKL 128
#define NCHK  (LSEQ / CHUNKL)     // 32
#define NCHUNK 48                 // 3 segments * (1024/64)

// ---------------- device scratch ----------------
__device__ float g_lb   [2 * PDIM];
__device__ float g_lb128[2 * PDIM];
__device__ float g_fac  [2 * PDIM];
__device__ __nv_bfloat16 g_ub [(size_t)MTOT * KSPL];
__device__ __nv_bfloat16 g_w1b[(size_t)1024 * KSPL];
__device__ __nv_bfloat16 g_w2b[(size_t)1024 * KSPL];
__device__ float g_Bu [(size_t)MTOT * 1024];
__device__ __nv_bfloat16 g_xsb[(size_t)MTOT * KSPL];
__device__ float g_cs_re[BSZ * NCHK * PDIM];
__device__ float g_cs_im[BSZ * NCHK * PDIM];
__device__ float g_ci_re[BSZ * NCHK * PDIM];
__device__ float g_ci_im[BSZ * NCHK * PDIM];

// ---------------- PTX helpers ----------------
__device__ __forceinline__ uint32_t smem_u32(const void* p) {
    uint32_t a;
    asm("{ .reg .u64 t; cvta.to.shared.u64 t, %1; cvt.u32.u64 %0, t; }" : "=r"(a) : "l"(p));
    return a;
}
#define CP_ASYNC16(dst, src) \
    asm volatile("cp.async.cg.shared.global [%0], [%1], 16;" :: "r"(dst), "l"(src) : "memory")
#define CP_COMMIT() asm volatile("cp.async.commit_group;" ::: "memory")
#define CP_WAIT1()  asm volatile("cp.async.wait_group 1;" ::: "memory")

__device__ __forceinline__ void ldsm4(uint32_t* r, uint32_t addr) {
    asm volatile("ldmatrix.sync.aligned.m8n8.x4.shared.b16 {%0,%1,%2,%3}, [%4];"
                 : "=r"(r[0]), "=r"(r[1]), "=r"(r[2]), "=r"(r[3]) : "r"(addr));
}
__device__ __forceinline__ void mma16816(float* d, const uint32_t* a, uint32_t b0, uint32_t b1) {
    asm volatile("mma.sync.aligned.m16n8k16.row.col.f32.bf16.bf16.f32 "
                 "{%0,%1,%2,%3}, {%4,%5,%6,%7}, {%8,%9}, {%0,%1,%2,%3};"
                 : "+f"(d[0]), "+f"(d[1]), "+f"(d[2]), "+f"(d[3])
                 : "r"(a[0]), "r"(a[1]), "r"(a[2]), "r"(a[3]), "r"(b0), "r"(b1));
}
#define SWZ(x) ((x) ^ (((x) >> 3) & 0x70))

// ---------------- param prep ----------------
__global__ void prep_lambda_kernel(const float* __restrict__ Lre,
                                   const float* __restrict__ Lim,
                                   const float* __restrict__ lstep)
{
    int p = blockIdx.x * blockDim.x + threadIdx.x;
    if (p >= PDIM) return;
    double lr = fmin((double)Lre[p], -1e-4);
    double li = (double)Lim[p];
    double s  = exp((double)lstep[p]);
    double er = exp(lr * s), th = li * s;
    double lbre = er * cos(th), lbim = er * sin(th);
    double den = lr * lr + li * li;
    double gre = lbre - 1.0, gim = lbim;
    g_lb[p]         = (float)lbre;
    g_lb[PDIM + p]  = (float)lbim;
    g_fac[p]        = (float)((gre * lr + gim * li) / den);
    g_fac[PDIM + p] = (float)((gim * lr - gre * li) / den);
    double er128 = exp(128.0 * lr * s), th128 = 128.0 * li * s;
    g_lb128[p]        = (float)(er128 * cos(th128));
    g_lb128[PDIM + p] = (float)(er128 * sin(th128));
}

__device__ __forceinline__ void split2(float x, __nv_bfloat16& h, __nv_bfloat16& l) {
    h = __float2bfloat16_rn(x);
    l = __float2bfloat16_rn(x - __bfloat162float(h));
}

__global__ void split_u_kernel(const float* __restrict__ u)
{
    size_t idx = (size_t)blockIdx.x * blockDim.x + threadIdx.x;
    size_t r = idx >> 8;
    int c = (int)(idx & 255) * 4;
    float4 v = *(const float4*)(u + r * 1024 + c);
    __nv_bfloat16 h0,h1,h2,h3,l0,l1,l2,l3;
    split2(v.x,h0,l0); split2(v.y,h1,l1); split2(v.z,h2,l2); split2(v.w,h3,l3);
    __nv_bfloat16* o = g_ub + r * KSPL;
    *(__nv_bfloat162*)(o + c)          = __halves2bfloat162(h0, h1);
    *(__nv_bfloat162*)(o + c + 2)      = __halves2bfloat162(h2, h3);
    *(__nv_bfloat162*)(o + 1024 + c)   = __halves2bfloat162(l0, l1);
    *(__nv_bfloat162*)(o + 1024 + c+2) = __halves2bfloat162(l2, l3);
}

__global__ void split_w1_kernel(const float* __restrict__ Bp)  // (P,H,2)
{
    int idx = blockIdx.x * blockDim.x + threadIdx.x;
    if (idx >= PDIM * HDIM) return;
    int p = idx >> 10, h = idx & 1023;
    float b0 = Bp[p * 2048 + h * 2 + 0];
    float b1 = Bp[p * 2048 + h * 2 + 1];
    float fr = g_fac[p], fi = g_fac[PDIM + p];
    float wre = fr * b0 - fi * b1;
    float wim = fr * b1 + fi * b0;
    __nv_bfloat16 hh, ll;
    split2(wre, hh, ll);
    g_w1b[(size_t)p * KSPL + h] = hh;
    g_w1b[(size_t)p * KSPL + 1024 + h] = ll;
    split2(wim, hh, ll);
    g_w1b[(size_t)(PDIM + p) * KSPL + h] = hh;
    g_w1b[(size_t)(PDIM + p) * KSPL + 1024 + h] = ll;
}

__global__ void split_w2_kernel(const float* __restrict__ Cp)  // (H,P,2)
{
    int idx = blockIdx.x * blockDim.x + threadIdx.x;
    if (idx >= HDIM * PDIM) return;
    int h = idx >> 9, p = idx & 511;
    float cre =  Cp[h * 1024 + p * 2 + 0];
    float cim = -Cp[h * 1024 + p * 2 + 1];
    __nv_bfloat16 hh, ll;
    split2(cre, hh, ll);
    g_w2b[(size_t)h * KSPL + p] = hh;
    g_w2b[(size_t)h * KSPL + 1024 + p] = ll;
    split2(cim, hh, ll);
    g_w2b[(size_t)h * KSPL + 512 + p] = hh;
    g_w2b[(size_t)h * KSPL + 1024 + 512 + p] = ll;
}

// ---------------- HMMA GEMM: C(128x128 tiles) = A * B^T over mapped K=3072 ----
// A (MTOT x 2048 bf16, [hi|lo]), B (1024 x 2048 bf16, [hi|lo]).
// 48 chunks of BK=64: seg0 Ah*Bh, seg1 Ah*Bl, seg2 Al*Bh.
#define STAGE_BYTES 32768
#define SMEM_SZ (3 * STAGE_BYTES)

__device__ __forceinline__ void load_chunk_async(
    const __nv_bfloat16* __restrict__ A, const __nv_bfloat16* __restrict__ B,
    int bm, int bn, int c, uint32_t sA, uint32_t sB, int tid)
{
    int seg = c >> 4, cc = c & 15;
    int acol = ((seg == 2) ? 1024 : 0) + cc * 64;
    int bcol = ((seg == 1) ? 1024 : 0) + cc * 64;
    const char* Ag = (const char*)(A + (size_t)bm * KSPL + acol);
    const char* Bg = (const char*)(B + (size_t)bn * KSPL + bcol);
    #pragma unroll
    for (int i = 0; i < 4; i++) {
        int idx = tid + (i << 8);
        int row = idx >> 3, ch = (idx & 7) << 4;
        CP_ASYNC16(sA + SWZ(row * 128 + ch), Ag + (size_t)row * 4096 + ch);
    }
    #pragma unroll
    for (int i = 0; i < 4; i++) {
        int idx = tid + (i << 8);
        int row = idx >> 3, ch = (idx & 7) << 4;
        CP_ASYNC16(sB + SWZ(row * 128 + ch), Bg + (size_t)row * 4096 + ch);
    }
}

template<bool EPI>
__global__ void __launch_bounds__(256, 1)
gemm_mma(const __nv_bfloat16* __restrict__ A, const __nv_bfloat16* __restrict__ Bm,
         float* __restrict__ C, const float* __restrict__ Dv, const float* __restrict__ U)
{
    extern __shared__ char smem[];
    const uint32_t sbase = smem_u32(smem);
    const int tid = threadIdx.x;
    const int lane = tid & 31, wid = tid >> 5;
    const int wm = wid & 3, wn = wid >> 2;   // 4 x 2 warp grid: 32 rows x 64 cols each
    const int bm = blockIdx.y * 128, bn = blockIdx.x * 128;

    uint32_t sA[3], sB[3];
    #pragma unroll
    for (int s = 0; s < 3; s++) { sA[s] = sbase + s * STAGE_BYTES; sB[s] = sA[s] + 16384; }

    load_chunk_async(A, Bm, bm, bn, 0, sA[0], sB[0], tid); CP_COMMIT();
    load_chunk_async(A, Bm, bm, bn, 1, sA[1], sB[1], tid); CP_COMMIT();

    float acc[2][8][4];
    #pragma unroll
    for (int i = 0; i < 2; i++)
        #pragma unroll
        for (int j = 0; j < 8; j++)
            #pragma unroll
            for (int k = 0; k < 4; k++) acc[i][j][k] = 0.0f;

    const int arow = wm * 32 + (lane & 15);
    const int brow = wn * 64 + (lane & 15);
    const int khalf = (lane >> 4) * 16;

    #pragma unroll 1
    for (int c = 0; c < NCHUNK; c++) {
        CP_WAIT1();
        __syncthreads();
        if (c + 2 < NCHUNK)
            load_chunk_async(A, Bm, bm, bn, c + 2, sA[(c + 2) % 3], sB[(c + 2) % 3], tid);
        CP_COMMIT();

        const uint32_t a = sA[c % 3], b = sB[c % 3];
        #pragma unroll
        for (int ks = 0; ks < 4; ks++) {
            const int kb = ks * 32 + khalf;
            uint32_t af0[4], af1[4];
            ldsm4(af0, a + SWZ(arow * 128 + kb));
            ldsm4(af1, a + SWZ((arow + 16) * 128 + kb));
            #pragma unroll
            for (int np = 0; np < 4; np++) {
                uint32_t bf[4];
                ldsm4(bf, b + SWZ((brow + np * 16) * 128 + kb));
                // {bf[0],bf[2]} -> n-tile 2*np ; {bf[1],bf[3]} -> n-tile 2*np+1
                mma16816(acc[0][np * 2 + 0], af0, bf[0], bf[2]);
                mma16816(acc[0][np * 2 + 1], af0, bf[1], bf[3]);
                mma16816(acc[1][np * 2 + 0], af1, bf[0], bf[2]);
                mma16816(acc[1][np * 2 + 1], af1, bf[1], bf[3]);
            }
        }
    }

    // epilogue: acc -> global (optionally + D*U)
    #pragma unroll
    for (int mt = 0; mt < 2; mt++) {
        #pragma unroll
        for (int nt = 0; nt < 8; nt++) {
            const int row = bm + wm * 32 + mt * 16 + (lane >> 2);
            const int col = bn + wn * 64 + nt * 8 + (lane & 3) * 2;
            float d0 = acc[mt][nt][0], d1 = acc[mt][nt][1];
            float d2 = acc[mt][nt][2], d3 = acc[mt][nt][3];
            if (EPI) {
                float2 dv = *(const float2*)(Dv + col);
                float2 u0 = *(const float2*)(U + (size_t)row * 1024 + col);
                float2 u1 = *(const float2*)(U + (size_t)(row + 8) * 1024 + col);
                d0 = fmaf(dv.x, u0.x, d0); d1 = fmaf(dv.y, u0.y, d1);
                d2 = fmaf(dv.x, u1.x, d2); d3 = fmaf(dv.y, u1.y, d3);
            }
            *(float2*)(C + (size_t)row * 1024 + col)       = make_float2(d0, d1);
            *(float2*)(C + (size_t)(row + 8) * 1024 + col) = make_float2(d2, d3);
        }
    }
}

// ---------------- chunked parallel scan ----------------
__global__ void scan_pass1()
{
    int idx = blockIdx.x * blockDim.x + threadIdx.x;   // 131072
    int b = idx >> 14, k = (idx >> 9) & 31, p = idx & 511;
    const float lre = g_lb[p], lim = g_lb[PDIM + p];
    const float* __restrict__ bu = g_Bu + ((size_t)(b * LSEQ + k * CHUNKL)) * 1024;
    float xr = 0.0f, xi = 0.0f;
    #pragma unroll 4
    for (int l = 0; l < CHUNKL; l++) {
        float br = bu[(size_t)l * 1024 + p];
        float bi = bu[(size_t)l * 1024 + PDIM + p];
        float nr = fmaf(lre, xr, fmaf(-lim, xi, br));
        float ni = fmaf(lre, xi, fmaf( lim, xr, bi));
        xr = nr; xi = ni;
    }
    g_cs_re[idx] = xr;
    g_cs_im[idx] = xi;
}

__global__ void scan_pass2()
{
    int idx = blockIdx.x * blockDim.x + threadIdx.x;   // 4096
    int b = idx >> 9, p = idx & 511;
    const float ar = g_lb128[p], ai = g_lb128[PDIM + p];
    float cr = 0.0f, ci = 0.0f;
    for (int k = 0; k < NCHK; k++) {
        int j = (b * NCHK + k) * PDIM + p;
        g_ci_re[j] = cr; g_ci_im[j] = ci;
        float sr = g_cs_re[j], si = g_cs_im[j];
        float nr = fmaf(ar, cr, fmaf(-ai, ci, sr));
        float ni = fmaf(ar, ci, fmaf( ai, cr, si));
        cr = nr; ci = ni;
    }
}

__global__ void scan_pass3()
{
    int idx = blockIdx.x * blockDim.x + threadIdx.x;   // 131072
    int b = idx >> 14, k = (idx >> 9) & 31, p = idx & 511;
    const float lre = g_lb[p], lim = g_lb[PDIM + p];
    const float* __restrict__ bu = g_Bu + ((size_t)(b * LSEQ + k * CHUNKL)) * 1024;
    __nv_bfloat16* __restrict__ xo = g_xsb + ((size_t)(b * LSEQ + k * CHUNKL)) * KSPL;
    float xr = g_ci_re[idx], xi = g_ci_im[idx];
    #pragma unroll 4
    for (int l = 0; l < CHUNKL; l++) {
        float br = bu[(size_t)l * 1024 + p];
        float bi = bu[(size_t)l * 1024 + PDIM + p];
        float nr = fmaf(lre, xr, fmaf(-lim, xi, br));
        float ni = fmaf(lre, xi, fmaf( lim, xr, bi));
        xr = nr; xi = ni;
        __nv_bfloat16 h, l2;
        __nv_bfloat16* o = xo + (size_t)l * KSPL;
        split2(xr, h, l2);
        o[p] = h; o[1024 + p] = l2;
        split2(xi, h, l2);
        o[512 + p] = h; o[1536 + p] = l2;
    }
}

// ---------------- launcher ----------------
extern "C" void kernel_launch(void* const* d_in, const int* in_sizes, int n_in,
                              void* d_out, int out_size)
{
    const float* u     = (const float*)d_in[0];
    const float* Lre   = (const float*)d_in[1];
    const float* Lim   = (const float*)d_in[2];
    const float* Bp    = (const float*)d_in[3];
    const float* Cp    = (const float*)d_in[4];
    const float* Dv    = (const float*)d_in[5];
    const float* lstep = (const float*)d_in[6];
    float* out = (float*)d_out;

    void *pub, *pw1, *pw2, *pBu, *pxs;
    cudaGetSymbolAddress(&pub, g_ub);
    cudaGetSymbolAddress(&pw1, g_w1b);
    cudaGetSymbolAddress(&pw2, g_w2b);
    cudaGetSymbolAddress(&pBu, g_Bu);
    cudaGetSymbolAddress(&pxs, g_xsb);

    cudaFuncSetAttribute(gemm_mma<false>, cudaFuncAttributeMaxDynamicSharedMemorySize, SMEM_SZ);
    cudaFuncSetAttribute(gemm_mma<true>,  cudaFuncAttributeMaxDynamicSharedMemorySize, SMEM_SZ);

    prep_lambda_kernel<<<2, 256>>>(Lre, Lim, lstep);
    split_u_kernel<<<MTOT, 256>>>(u);
    split_w1_kernel<<<(PDIM * HDIM) / 256, 256>>>(Bp);
    split_w2_kernel<<<(HDIM * PDIM) / 256, 256>>>(Cp);

    dim3 grid(1024 / 128, MTOT / 128);   // (8, 256)
    gemm_mma<false><<<grid, 256, SMEM_SZ>>>((const __nv_bfloat16*)pub,
                                            (const __nv_bfloat16*)pw1,
                                            (float*)pBu, nullptr, nullptr);
    scan_pass1<<<512, 256>>>();
    scan_pass2<<<16, 256>>>();
    scan_pass3<<<512, 256>>>();
    gemm_mma<true><<<grid, 256, SMEM_SZ>>>((const __nv_bfloat16*)pxs,
                                           (const __nv_bfloat16*)pw2,
                                           out, Dv, u);
}

// round 4
// speedup vs baseline: 5.4857x; 1.7413x over previous
#include <cuda_runtime.h>
#include <cuda_fp16.h>
#include <math.h>
#include <stdint.h>

// ---------------- problem dims (fixed) ----------------
#define BSZ   8
#define LSEQ  4096
#define HDIM  1024
#define PDIM  512
#define MTOT  (BSZ * LSEQ)        // 32768
#define CHUNKL 128
#define NCHK  (LSEQ / CHUNKL)     // 32

#define S1_SCALE 1024.0f          // W1 pre-scale (2^10)
#define S1_INV   (1.0f / 1024.0f)
#define S2_SCALE 16384.0f         // W2 pre-scale (2^14)
#define S2_INV   (1.0f / 16384.0f)

// ---------------- device scratch ----------------
__device__ float g_lb   [2 * PDIM];
__device__ float g_lb128[2 * PDIM];
__device__ float g_fac  [2 * PDIM];
__device__ __half g_uh  [(size_t)MTOT * 1024];   // u fp16
__device__ __half g_w1h [(size_t)1024 * 1024];   // W1 fp16 (scaled 2^10), rows: [Re(Bbar); Im(Bbar)]
__device__ __half g_w2h [(size_t)1024 * 2048];   // W2 fp16 hi|lo K-concat (scaled 2^14)
__device__ float g_Bu   [(size_t)MTOT * 1024];   // GEMM1 out (scaled 2^10)
__device__ __half g_xsh [(size_t)MTOT * 1024];   // xs fp16 [re|im]
__device__ float g_cs_re[BSZ * NCHK * PDIM];
__device__ float g_cs_im[BSZ * NCHK * PDIM];
__device__ float g_ci_re[BSZ * NCHK * PDIM];
__device__ float g_ci_im[BSZ * NCHK * PDIM];

// ---------------- PTX helpers ----------------
__device__ __forceinline__ uint32_t smem_u32(const void* p) {
    uint32_t a;
    asm("{ .reg .u64 t; cvta.to.shared.u64 t, %1; cvt.u32.u64 %0, t; }" : "=r"(a) : "l"(p));
    return a;
}
#define CP_ASYNC16(dst, src) \
    asm volatile("cp.async.cg.shared.global [%0], [%1], 16;" :: "r"(dst), "l"(src) : "memory")
#define CP_COMMIT() asm volatile("cp.async.commit_group;" ::: "memory")
#define CP_WAIT1()  asm volatile("cp.async.wait_group 1;" ::: "memory")

__device__ __forceinline__ void ldsm4(uint32_t* r, uint32_t addr) {
    asm volatile("ldmatrix.sync.aligned.m8n8.x4.shared.b16 {%0,%1,%2,%3}, [%4];"
                 : "=r"(r[0]), "=r"(r[1]), "=r"(r[2]), "=r"(r[3]) : "r"(addr));
}
__device__ __forceinline__ void mma16816(float* d, const uint32_t* a, uint32_t b0, uint32_t b1) {
    asm volatile("mma.sync.aligned.m16n8k16.row.col.f32.f16.f16.f32 "
                 "{%0,%1,%2,%3}, {%4,%5,%6,%7}, {%8,%9}, {%0,%1,%2,%3};"
                 : "+f"(d[0]), "+f"(d[1]), "+f"(d[2]), "+f"(d[3])
                 : "r"(a[0]), "r"(a[1]), "r"(a[2]), "r"(a[3]), "r"(b0), "r"(b1));
}
#define SWZ(x) ((x) ^ (((x) >> 3) & 0x70))

// ---------------- param prep ----------------
__global__ void prep_lambda_kernel(const float* __restrict__ Lre,
                                   const float* __restrict__ Lim,
                                   const float* __restrict__ lstep)
{
    int p = blockIdx.x * blockDim.x + threadIdx.x;
    if (p >= PDIM) return;
    double lr = fmin((double)Lre[p], -1e-4);
    double li = (double)Lim[p];
    double s  = exp((double)lstep[p]);
    double er = exp(lr * s), th = li * s;
    double lbre = er * cos(th), lbim = er * sin(th);
    double den = lr * lr + li * li;
    double gre = lbre - 1.0, gim = lbim;
    g_lb[p]         = (float)lbre;
    g_lb[PDIM + p]  = (float)lbim;
    g_fac[p]        = (float)((gre * lr + gim * li) / den);
    g_fac[PDIM + p] = (float)((gim * lr - gre * li) / den);
    double er128 = exp(128.0 * lr * s), th128 = 128.0 * li * s;
    g_lb128[p]        = (float)(er128 * cos(th128));
    g_lb128[PDIM + p] = (float)(er128 * sin(th128));
}

__global__ void split_u_kernel(const float* __restrict__ u)
{
    size_t idx = (size_t)blockIdx.x * blockDim.x + threadIdx.x;  // MTOT*256
    size_t r = idx >> 8;
    int c = (int)(idx & 255) * 4;
    float4 v = *(const float4*)(u + r * 1024 + c);
    __half* o = g_uh + r * 1024;
    *(__half2*)(o + c)     = __floats2half2_rn(v.x, v.y);
    *(__half2*)(o + c + 2) = __floats2half2_rn(v.z, v.w);
}

__global__ void split_w1_kernel(const float* __restrict__ Bp)  // (P,H,2)
{
    int idx = blockIdx.x * blockDim.x + threadIdx.x;
    if (idx >= PDIM * HDIM) return;
    int p = idx >> 10, h = idx & 1023;
    float b0 = Bp[p * 2048 + h * 2 + 0];
    float b1 = Bp[p * 2048 + h * 2 + 1];
    float fr = g_fac[p], fi = g_fac[PDIM + p];
    float wre = (fr * b0 - fi * b1) * S1_SCALE;
    float wim = (fr * b1 + fi * b0) * S1_SCALE;
    g_w1h[(size_t)p * 1024 + h]          = __float2half_rn(wre);
    g_w1h[(size_t)(PDIM + p) * 1024 + h] = __float2half_rn(wim);
}

__global__ void split_w2_kernel(const float* __restrict__ Cp)  // (H,P,2)
{
    int idx = blockIdx.x * blockDim.x + threadIdx.x;
    if (idx >= HDIM * PDIM) return;
    int h = idx >> 9, p = idx & 511;
    float cre =  Cp[h * 1024 + p * 2 + 0] * S2_SCALE;
    float cim = -Cp[h * 1024 + p * 2 + 1] * S2_SCALE;
    __half hh;
    hh = __float2half_rn(cre);
    g_w2h[(size_t)h * 2048 + p] = hh;
    g_w2h[(size_t)h * 2048 + 1024 + p] = __float2half_rn(cre - __half2float(hh));
    hh = __float2half_rn(cim);
    g_w2h[(size_t)h * 2048 + 512 + p] = hh;
    g_w2h[(size_t)h * 2048 + 1024 + 512 + p] = __float2half_rn(cim - __half2float(hh));
}

// ---------------- HMMA fp16 GEMM: C(128x128 tiles) = A * B^T ----
// A: MTOT x 1024 fp16. B: 1024 rows x (BSTR) fp16 cols.
// NCH chunks of BK=64: acol = (c&15)*64 ; bcol = (c>>4)*1024 + (c&15)*64.
#define STAGE_BYTES 32768
#define SMEM_SZ (3 * STAGE_BYTES)

template<int BSTR>
__device__ __forceinline__ void load_chunk_async(
    const __half* __restrict__ A, const __half* __restrict__ B,
    int bm, int bn, int c, uint32_t sA, uint32_t sB, int tid)
{
    int acol = (c & 15) * 64;
    int bcol = (c >> 4) * 1024 + (c & 15) * 64;
    const char* Ag = (const char*)(A + (size_t)bm * 1024 + acol);
    const char* Bg = (const char*)(B + (size_t)bn * BSTR + bcol);
    #pragma unroll
    for (int i = 0; i < 4; i++) {
        int idx = tid + (i << 8);
        int row = idx >> 3, ch = (idx & 7) << 4;
        CP_ASYNC16(sA + SWZ(row * 128 + ch), Ag + (size_t)row * 2048 + ch);
    }
    #pragma unroll
    for (int i = 0; i < 4; i++) {
        int idx = tid + (i << 8);
        int row = idx >> 3, ch = (idx & 7) << 4;
        CP_ASYNC16(sB + SWZ(row * 128 + ch), Bg + (size_t)row * (BSTR * 2) + ch);
    }
}

template<int NCH, int BSTR, bool EPI>
__global__ void __launch_bounds__(256, 1)
gemm_mma(const __half* __restrict__ A, const __half* __restrict__ Bm,
         float* __restrict__ C, const float* __restrict__ Dv, const float* __restrict__ U)
{
    extern __shared__ char smem[];
    const uint32_t sbase = smem_u32(smem);
    const int tid = threadIdx.x;
    const int lane = tid & 31, wid = tid >> 5;
    const int wm = wid & 3, wn = wid >> 2;   // 4 x 2 warp grid: 32 rows x 64 cols each
    const int bm = blockIdx.y * 128, bn = blockIdx.x * 128;

    uint32_t sA[3], sB[3];
    #pragma unroll
    for (int s = 0; s < 3; s++) { sA[s] = sbase + s * STAGE_BYTES; sB[s] = sA[s] + 16384; }

    load_chunk_async<BSTR>(A, Bm, bm, bn, 0, sA[0], sB[0], tid); CP_COMMIT();
    load_chunk_async<BSTR>(A, Bm, bm, bn, 1, sA[1], sB[1], tid); CP_COMMIT();

    float acc[2][8][4];
    #pragma unroll
    for (int i = 0; i < 2; i++)
        #pragma unroll
        for (int j = 0; j < 8; j++)
            #pragma unroll
            for (int k = 0; k < 4; k++) acc[i][j][k] = 0.0f;

    const int arow = wm * 32 + (lane & 15);
    const int brow = wn * 64 + (lane & 15);
    const int khalf = (lane >> 4) * 16;

    #pragma unroll 1
    for (int c = 0; c < NCH; c++) {
        CP_WAIT1();
        __syncthreads();
        if (c + 2 < NCH)
            load_chunk_async<BSTR>(A, Bm, bm, bn, c + 2, sA[(c + 2) % 3], sB[(c + 2) % 3], tid);
        CP_COMMIT();

        const uint32_t a = sA[c % 3], b = sB[c % 3];
        #pragma unroll
        for (int ks = 0; ks < 4; ks++) {
            const int kb = ks * 32 + khalf;
            uint32_t af0[4], af1[4];
            ldsm4(af0, a + SWZ(arow * 128 + kb));
            ldsm4(af1, a + SWZ((arow + 16) * 128 + kb));
            #pragma unroll
            for (int np = 0; np < 4; np++) {
                uint32_t bf[4];
                ldsm4(bf, b + SWZ((brow + np * 16) * 128 + kb));
                mma16816(acc[0][np * 2 + 0], af0, bf[0], bf[2]);
                mma16816(acc[0][np * 2 + 1], af0, bf[1], bf[3]);
                mma16816(acc[1][np * 2 + 0], af1, bf[0], bf[2]);
                mma16816(acc[1][np * 2 + 1], af1, bf[1], bf[3]);
            }
        }
    }

    // epilogue
    #pragma unroll
    for (int mt = 0; mt < 2; mt++) {
        #pragma unroll
        for (int nt = 0; nt < 8; nt++) {
            const int row = bm + wm * 32 + mt * 16 + (lane >> 2);
            const int col = bn + wn * 64 + nt * 8 + (lane & 3) * 2;
            float d0 = acc[mt][nt][0], d1 = acc[mt][nt][1];
            float d2 = acc[mt][nt][2], d3 = acc[mt][nt][3];
            if (EPI) {
                d0 *= S2_INV; d1 *= S2_INV; d2 *= S2_INV; d3 *= S2_INV;
                float2 dv = *(const float2*)(Dv + col);
                float2 u0 = *(const float2*)(U + (size_t)row * 1024 + col);
                float2 u1 = *(const float2*)(U + (size_t)(row + 8) * 1024 + col);
                d0 = fmaf(dv.x, u0.x, d0); d1 = fmaf(dv.y, u0.y, d1);
                d2 = fmaf(dv.x, u1.x, d2); d3 = fmaf(dv.y, u1.y, d3);
            }
            *(float2*)(C + (size_t)row * 1024 + col)       = make_float2(d0, d1);
            *(float2*)(C + (size_t)(row + 8) * 1024 + col) = make_float2(d2, d3);
        }
    }
}

// ---------------- chunked parallel scan (Bu is scaled by 2^10) ----------------
__global__ void scan_pass1()
{
    int idx = blockIdx.x * blockDim.x + threadIdx.x;   // 131072
    int b = idx >> 14, k = (idx >> 9) & 31, p = idx & 511;
    const float lre = g_lb[p], lim = g_lb[PDIM + p];
    const float* __restrict__ bu = g_Bu + ((size_t)(b * LSEQ + k * CHUNKL)) * 1024;
    float xr = 0.0f, xi = 0.0f;
    #pragma unroll 4
    for (int l = 0; l < CHUNKL; l++) {
        float br = bu[(size_t)l * 1024 + p] * S1_INV;
        float bi = bu[(size_t)l * 1024 + PDIM + p] * S1_INV;
        float nr = fmaf(lre, xr, fmaf(-lim, xi, br));
        float ni = fmaf(lre, xi, fmaf( lim, xr, bi));
        xr = nr; xi = ni;
    }
    g_cs_re[idx] = xr;
    g_cs_im[idx] = xi;
}

__global__ void scan_pass2()
{
    int idx = blockIdx.x * blockDim.x + threadIdx.x;   // 4096
    int b = idx >> 9, p = idx & 511;
    const float ar = g_lb128[p], ai = g_lb128[PDIM + p];
    float cr = 0.0f, ci = 0.0f;
    for (int k = 0; k < NCHK; k++) {
        int j = (b * NCHK + k) * PDIM + p;
        g_ci_re[j] = cr; g_ci_im[j] = ci;
        float sr = g_cs_re[j], si = g_cs_im[j];
        float nr = fmaf(ar, cr, fmaf(-ai, ci, sr));
        float ni = fmaf(ar, ci, fmaf( ai, cr, si));
        cr = nr; ci = ni;
    }
}

__global__ void scan_pass3()
{
    int idx = blockIdx.x * blockDim.x + threadIdx.x;   // 131072
    int b = idx >> 14, k = (idx >> 9) & 31, p = idx & 511;
    const float lre = g_lb[p], lim = g_lb[PDIM + p];
    const float* __restrict__ bu = g_Bu + ((size_t)(b * LSEQ + k * CHUNKL)) * 1024;
    __half* __restrict__ xo = g_xsh + ((size_t)(b * LSEQ + k * CHUNKL)) * 1024;
    float xr = g_ci_re[idx], xi = g_ci_im[idx];
    #pragma unroll 4
    for (int l = 0; l < CHUNKL; l++) {
        float br = bu[(size_t)l * 1024 + p] * S1_INV;
        float bi = bu[(size_t)l * 1024 + PDIM + p] * S1_INV;
        float nr = fmaf(lre, xr, fmaf(-lim, xi, br));
        float ni = fmaf(lre, xi, fmaf( lim, xr, bi));
        xr = nr; xi = ni;
        __half* o = xo + (size_t)l * 1024;
        o[p]        = __float2half_rn(xr);
        o[PDIM + p] = __float2half_rn(xi);
    }
}

// ---------------- launcher ----------------
extern "C" void kernel_launch(void* const* d_in, const int* in_sizes, int n_in,
                              void* d_out, int out_size)
{
    const float* u     = (const float*)d_in[0];
    const float* Lre   = (const float*)d_in[1];
    const float* Lim   = (const float*)d_in[2];
    const float* Bp    = (const float*)d_in[3];
    const float* Cp    = (const float*)d_in[4];
    const float* Dv    = (const float*)d_in[5];
    const float* lstep = (const float*)d_in[6];
    float* out = (float*)d_out;

    void *puh, *pw1, *pw2, *pBu, *pxs;
    cudaGetSymbolAddress(&puh, g_uh);
    cudaGetSymbolAddress(&pw1, g_w1h);
    cudaGetSymbolAddress(&pw2, g_w2h);
    cudaGetSymbolAddress(&pBu, g_Bu);
    cudaGetSymbolAddress(&pxs, g_xsh);

    cudaFuncSetAttribute((const void*)gemm_mma<16, 1024, false>,
                         cudaFuncAttributeMaxDynamicSharedMemorySize, SMEM_SZ);
    cudaFuncSetAttribute((const void*)gemm_mma<32, 2048, true>,
                         cudaFuncAttributeMaxDynamicSharedMemorySize, SMEM_SZ);

    prep_lambda_kernel<<<2, 256>>>(Lre, Lim, lstep);
    split_u_kernel<<<MTOT, 256>>>(u);
    split_w1_kernel<<<(PDIM * HDIM) / 256, 256>>>(Bp);
    split_w2_kernel<<<(HDIM * PDIM) / 256, 256>>>(Cp);

    dim3 grid(1024 / 128, MTOT / 128);   // (8, 256)
    // GEMM1: Bu = u @ W1^T   (single-term fp16, K=1024)
    gemm_mma<16, 1024, false><<<grid, 256, SMEM_SZ>>>((const __half*)puh,
                                                      (const __half*)pw1,
                                                      (float*)pBu, nullptr, nullptr);
    scan_pass1<<<512, 256>>>();
    scan_pass2<<<16, 256>>>();
    scan_pass3<<<512, 256>>>();
    // GEMM2: ys = xs @ W2^T + D*u  (A single fp16, B hi+lo K=2048)
    gemm_mma<32, 2048, true><<<grid, 256, SMEM_SZ>>>((const __half*)pxs,
                                                     (const __half*)pw2,
                                                     out, Dv, u);
}

// round 5
// speedup vs baseline: 8.9105x; 1.6243x over previous
#include <cuda_runtime.h>
#include <cuda_fp16.h>
#include <math.h>
#include <stdint.h>

// ---------------- problem dims (fixed) ----------------
#define BSZ   8
#define LSEQ  4096
#define HDIM  1024
#define PDIM  512
#define MTOT  (BSZ * LSEQ)        // 32768
#define CHUNKL 128
#define NCHK  (LSEQ / CHUNKL)     // 32

#define S1_SCALE 1024.0f          // W1 pre-scale (2^10) keeps entries in fp16 normal range
#define S1_INV   (1.0f / 1024.0f)

// ---------------- device scratch ----------------
__device__ float g_lb   [2 * PDIM];
__device__ float g_lb128[2 * PDIM];
__device__ float g_fac  [2 * PDIM];
__device__ __half g_uh  [(size_t)MTOT * 1024];   // u fp16
__device__ __half g_w1h [(size_t)1024 * 1024];   // W1 fp16 (scaled 2^10): [Re(Bbar); Im(Bbar)]
__device__ __half g_w2h [(size_t)1024 * 1024];   // W2 fp16: [C_re | -C_im] per row
__device__ float g_Bu   [(size_t)MTOT * 1024];   // GEMM1 out (scaled 2^10)
__device__ __half g_xsh [(size_t)MTOT * 1024];   // xs fp16 [re|im]
__device__ float g_cs_re[BSZ * NCHK * PDIM];
__device__ float g_cs_im[BSZ * NCHK * PDIM];
__device__ float g_ci_re[BSZ * NCHK * PDIM];
__device__ float g_ci_im[BSZ * NCHK * PDIM];

// ---------------- PTX helpers ----------------
__device__ __forceinline__ uint32_t smem_u32(const void* p) {
    uint32_t a;
    asm("{ .reg .u64 t; cvta.to.shared.u64 t, %1; cvt.u32.u64 %0, t; }" : "=r"(a) : "l"(p));
    return a;
}
#define CP_ASYNC16(dst, src) \
    asm volatile("cp.async.cg.shared.global [%0], [%1], 16;" :: "r"(dst), "l"(src) : "memory")
#define CP_COMMIT() asm volatile("cp.async.commit_group;" ::: "memory")
#define CP_WAIT1()  asm volatile("cp.async.wait_group 1;" ::: "memory")

__device__ __forceinline__ void ldsm4(uint32_t* r, uint32_t addr) {
    asm volatile("ldmatrix.sync.aligned.m8n8.x4.shared.b16 {%0,%1,%2,%3}, [%4];"
                 : "=r"(r[0]), "=r"(r[1]), "=r"(r[2]), "=r"(r[3]) : "r"(addr));
}
__device__ __forceinline__ void mma16816(float* d, const uint32_t* a, uint32_t b0, uint32_t b1) {
    asm volatile("mma.sync.aligned.m16n8k16.row.col.f32.f16.f16.f32 "
                 "{%0,%1,%2,%3}, {%4,%5,%6,%7}, {%8,%9}, {%0,%1,%2,%3};"
                 : "+f"(d[0]), "+f"(d[1]), "+f"(d[2]), "+f"(d[3])
                 : "r"(a[0]), "r"(a[1]), "r"(a[2]), "r"(a[3]), "r"(b0), "r"(b1));
}
#define SWZ(x) ((x) ^ (((x) >> 3) & 0x70))

// ---------------- param prep ----------------
__global__ void prep_lambda_kernel(const float* __restrict__ Lre,
                                   const float* __restrict__ Lim,
                                   const float* __restrict__ lstep)
{
    int p = blockIdx.x * blockDim.x + threadIdx.x;
    if (p >= PDIM) return;
    double lr = fmin((double)Lre[p], -1e-4);
    double li = (double)Lim[p];
    double s  = exp((double)lstep[p]);
    double er = exp(lr * s), th = li * s;
    double lbre = er * cos(th), lbim = er * sin(th);
    double den = lr * lr + li * li;
    double gre = lbre - 1.0, gim = lbim;
    g_lb[p]         = (float)lbre;
    g_lb[PDIM + p]  = (float)lbim;
    g_fac[p]        = (float)((gre * lr + gim * li) / den);
    g_fac[PDIM + p] = (float)((gim * lr - gre * li) / den);
    double er128 = exp(128.0 * lr * s), th128 = 128.0 * li * s;
    g_lb128[p]        = (float)(er128 * cos(th128));
    g_lb128[PDIM + p] = (float)(er128 * sin(th128));
}

__global__ void split_u_kernel(const float* __restrict__ u)
{
    size_t idx = (size_t)blockIdx.x * blockDim.x + threadIdx.x;
    size_t r = idx >> 8;
    int c = (int)(idx & 255) * 4;
    float4 v = *(const float4*)(u + r * 1024 + c);
    __half* o = g_uh + r * 1024;
    *(__half2*)(o + c)     = __floats2half2_rn(v.x, v.y);
    *(__half2*)(o + c + 2) = __floats2half2_rn(v.z, v.w);
}

__global__ void split_w1_kernel(const float* __restrict__ Bp)  // (P,H,2)
{
    int idx = blockIdx.x * blockDim.x + threadIdx.x;
    if (idx >= PDIM * HDIM) return;
    int p = idx >> 10, h = idx & 1023;
    float b0 = Bp[p * 2048 + h * 2 + 0];
    float b1 = Bp[p * 2048 + h * 2 + 1];
    float fr = g_fac[p], fi = g_fac[PDIM + p];
    g_w1h[(size_t)p * 1024 + h]          = __float2half_rn((fr * b0 - fi * b1) * S1_SCALE);
    g_w1h[(size_t)(PDIM + p) * 1024 + h] = __float2half_rn((fr * b1 + fi * b0) * S1_SCALE);
}

__global__ void split_w2_kernel(const float* __restrict__ Cp)  // (H,P,2)
{
    int idx = blockIdx.x * blockDim.x + threadIdx.x;
    if (idx >= HDIM * PDIM) return;
    int h = idx >> 9, p = idx & 511;
    g_w2h[(size_t)h * 1024 + p]        = __float2half_rn( Cp[h * 1024 + p * 2 + 0]);
    g_w2h[(size_t)h * 1024 + 512 + p]  = __float2half_rn(-Cp[h * 1024 + p * 2 + 1]);
}

// ---------------- HMMA fp16 GEMM: C = A(Mx1024) * B(1024x1024)^T ----
#define STAGE_BYTES 32768
#define SMEM_SZ (3 * STAGE_BYTES)
#define NCH 16

__device__ __forceinline__ void load_chunk_async(
    const __half* __restrict__ A, const __half* __restrict__ B,
    int bm, int bn, int c, uint32_t sA, uint32_t sB, int tid)
{
    int col = c * 64;
    const char* Ag = (const char*)(A + (size_t)bm * 1024 + col);
    const char* Bg = (const char*)(B + (size_t)bn * 1024 + col);
    #pragma unroll
    for (int i = 0; i < 4; i++) {
        int idx = tid + (i << 8);
        int row = idx >> 3, ch = (idx & 7) << 4;
        CP_ASYNC16(sA + SWZ(row * 128 + ch), Ag + (size_t)row * 2048 + ch);
    }
    #pragma unroll
    for (int i = 0; i < 4; i++) {
        int idx = tid + (i << 8);
        int row = idx >> 3, ch = (idx & 7) << 4;
        CP_ASYNC16(sB + SWZ(row * 128 + ch), Bg + (size_t)row * 2048 + ch);
    }
}

template<bool EPI>
__global__ void __launch_bounds__(256, 2)
gemm_mma(const __half* __restrict__ A, const __half* __restrict__ Bm,
         float* __restrict__ C, const float* __restrict__ Dv, const float* __restrict__ U)
{
    extern __shared__ char smem[];
    const uint32_t sbase = smem_u32(smem);
    const int tid = threadIdx.x;
    const int lane = tid & 31, wid = tid >> 5;
    const int wm = wid & 3, wn = wid >> 2;   // 4 x 2 warp grid: 32 rows x 64 cols each
    const int bm = blockIdx.y * 128, bn = blockIdx.x * 128;

    uint32_t sA[3], sB[3];
    #pragma unroll
    for (int s = 0; s < 3; s++) { sA[s] = sbase + s * STAGE_BYTES; sB[s] = sA[s] + 16384; }

    load_chunk_async(A, Bm, bm, bn, 0, sA[0], sB[0], tid); CP_COMMIT();
    load_chunk_async(A, Bm, bm, bn, 1, sA[1], sB[1], tid); CP_COMMIT();

    float acc[2][8][4];
    #pragma unroll
    for (int i = 0; i < 2; i++)
        #pragma unroll
        for (int j = 0; j < 8; j++)
            #pragma unroll
            for (int k = 0; k < 4; k++) acc[i][j][k] = 0.0f;

    const int arow = wm * 32 + (lane & 15);
    const int brow = wn * 64 + (lane & 15);
    const int khalf = (lane >> 4) * 16;

    #pragma unroll 1
    for (int c = 0; c < NCH; c++) {
        CP_WAIT1();
        __syncthreads();
        if (c + 2 < NCH)
            load_chunk_async(A, Bm, bm, bn, c + 2, sA[(c + 2) % 3], sB[(c + 2) % 3], tid);
        CP_COMMIT();

        const uint32_t a = sA[c % 3], b = sB[c % 3];
        #pragma unroll
        for (int ks = 0; ks < 4; ks++) {
            const int kb = ks * 32 + khalf;
            uint32_t af0[4], af1[4];
            ldsm4(af0, a + SWZ(arow * 128 + kb));
            ldsm4(af1, a + SWZ((arow + 16) * 128 + kb));
            #pragma unroll
            for (int np = 0; np < 4; np++) {
                uint32_t bf[4];
                ldsm4(bf, b + SWZ((brow + np * 16) * 128 + kb));
                mma16816(acc[0][np * 2 + 0], af0, bf[0], bf[2]);
                mma16816(acc[0][np * 2 + 1], af0, bf[1], bf[3]);
                mma16816(acc[1][np * 2 + 0], af1, bf[0], bf[2]);
                mma16816(acc[1][np * 2 + 1], af1, bf[1], bf[3]);
            }
        }
    }

    // epilogue
    #pragma unroll
    for (int mt = 0; mt < 2; mt++) {
        #pragma unroll
        for (int nt = 0; nt < 8; nt++) {
            const int row = bm + wm * 32 + mt * 16 + (lane >> 2);
            const int col = bn + wn * 64 + nt * 8 + (lane & 3) * 2;
            float d0 = acc[mt][nt][0], d1 = acc[mt][nt][1];
            float d2 = acc[mt][nt][2], d3 = acc[mt][nt][3];
            if (EPI) {
                float2 dv = *(const float2*)(Dv + col);
                float2 u0 = *(const float2*)(U + (size_t)row * 1024 + col);
                float2 u1 = *(const float2*)(U + (size_t)(row + 8) * 1024 + col);
                d0 = fmaf(dv.x, u0.x, d0); d1 = fmaf(dv.y, u0.y, d1);
                d2 = fmaf(dv.x, u1.x, d2); d3 = fmaf(dv.y, u1.y, d3);
            }
            *(float2*)(C + (size_t)row * 1024 + col)       = make_float2(d0, d1);
            *(float2*)(C + (size_t)(row + 8) * 1024 + col) = make_float2(d2, d3);
        }
    }
}

// ---------------- chunked parallel scan (Bu is scaled by 2^10) ----------------
__global__ void scan_pass1()
{
    int idx = blockIdx.x * blockDim.x + threadIdx.x;   // 131072
    int b = idx >> 14, k = (idx >> 9) & 31, p = idx & 511;
    const float lre = g_lb[p], lim = g_lb[PDIM + p];
    const float* __restrict__ bu = g_Bu + ((size_t)(b * LSEQ + k * CHUNKL)) * 1024;
    float xr = 0.0f, xi = 0.0f;
    #pragma unroll 4
    for (int l = 0; l < CHUNKL; l++) {
        float br = bu[(size_t)l * 1024 + p] * S1_INV;
        float bi = bu[(size_t)l * 1024 + PDIM + p] * S1_INV;
        float nr = fmaf(lre, xr, fmaf(-lim, xi, br));
        float ni = fmaf(lre, xi, fmaf( lim, xr, bi));
        xr = nr; xi = ni;
    }
    g_cs_re[idx] = xr;
    g_cs_im[idx] = xi;
}

__global__ void scan_pass2()
{
    int idx = blockIdx.x * blockDim.x + threadIdx.x;   // 4096
    int b = idx >> 9, p = idx & 511;
    const float ar = g_lb128[p], ai = g_lb128[PDIM + p];
    float cr = 0.0f, ci = 0.0f;
    for (int k = 0; k < NCHK; k++) {
        int j = (b * NCHK + k) * PDIM + p;
        g_ci_re[j] = cr; g_ci_im[j] = ci;
        float sr = g_cs_re[j], si = g_cs_im[j];
        float nr = fmaf(ar, cr, fmaf(-ai, ci, sr));
        float ni = fmaf(ar, ci, fmaf( ai, cr, si));
        cr = nr; ci = ni;
    }
}

__global__ void scan_pass3()
{
    int idx = blockIdx.x * blockDim.x + threadIdx.x;   // 131072
    int b = idx >> 14, k = (idx >> 9) & 31, p = idx & 511;
    const float lre = g_lb[p], lim = g_lb[PDIM + p];
    const float* __restrict__ bu = g_Bu + ((size_t)(b * LSEQ + k * CHUNKL)) * 1024;
    __half* __restrict__ xo = g_xsh + ((size_t)(b * LSEQ + k * CHUNKL)) * 1024;
    float xr = g_ci_re[idx], xi = g_ci_im[idx];
    #pragma unroll 4
    for (int l = 0; l < CHUNKL; l++) {
        float br = bu[(size_t)l * 1024 + p] * S1_INV;
        float bi = bu[(size_t)l * 1024 + PDIM + p] * S1_INV;
        float nr = fmaf(lre, xr, fmaf(-lim, xi, br));
        float ni = fmaf(lre, xi, fmaf( lim, xr, bi));
        xr = nr; xi = ni;
        __half* o = xo + (size_t)l * 1024;
        o[p]        = __float2half_rn(xr);
        o[PDIM + p] = __float2half_rn(xi);
    }
}

// ---------------- launcher ----------------
extern "C" void kernel_launch(void* const* d_in, const int* in_sizes, int n_in,
                              void* d_out, int out_size)
{
    const float* u     = (const float*)d_in[0];
    const float* Lre   = (const float*)d_in[1];
    const float* Lim   = (const float*)d_in[2];
    const float* Bp    = (const float*)d_in[3];
    const float* Cp    = (const float*)d_in[4];
    const float* Dv    = (const float*)d_in[5];
    const float* lstep = (const float*)d_in[6];
    float* out = (float*)d_out;

    void *puh, *pw1, *pw2, *pBu, *pxs;
    cudaGetSymbolAddress(&puh, g_uh);
    cudaGetSymbolAddress(&pw1, g_w1h);
    cudaGetSymbolAddress(&pw2, g_w2h);
    cudaGetSymbolAddress(&pBu, g_Bu);
    cudaGetSymbolAddress(&pxs, g_xsh);

    cudaFuncSetAttribute((const void*)gemm_mma<false>,
                         cudaFuncAttributeMaxDynamicSharedMemorySize, SMEM_SZ);
    cudaFuncSetAttribute((const void*)gemm_mma<true>,
                         cudaFuncAttributeMaxDynamicSharedMemorySize, SMEM_SZ);

    prep_lambda_kernel<<<2, 256>>>(Lre, Lim, lstep);
    split_u_kernel<<<MTOT, 256>>>(u);
    split_w1_kernel<<<(PDIM * HDIM) / 256, 256>>>(Bp);
    split_w2_kernel<<<(HDIM * PDIM) / 256, 256>>>(Cp);

    dim3 grid(1024 / 128, MTOT / 128);   // (8, 256)
    gemm_mma<false><<<grid, 256, SMEM_SZ>>>((const __half*)puh,
                                            (const __half*)pw1,
                                            (float*)pBu, nullptr, nullptr);
    scan_pass1<<<512, 256>>>();
    scan_pass2<<<16, 256>>>();
    scan_pass3<<<512, 256>>>();
    gemm_mma<true><<<grid, 256, SMEM_SZ>>>((const __half*)pxs,
                                           (const __half*)pw2,
                                           out, Dv, u);
}

// round 6
// speedup vs baseline: 9.0630x; 1.0171x over previous
#include <cuda_runtime.h>
#include <cuda_fp16.h>
#include <math.h>
#include <stdint.h>

// ---------------- problem dims (fixed) ----------------
#define BSZ   8
#define LSEQ  4096
#define HDIM  1024
#define PDIM  512
#define MTOT  (BSZ * LSEQ)        // 32768
#define CHUNKL 128
#define NCHK  (LSEQ / CHUNKL)     // 32

#define S1_SCALE 1024.0f          // W1 pre-scale (2^10); scan runs fully scaled
#define S1_INV   (1.0f / 1024.0f)

// ---------------- device scratch ----------------
__device__ float g_lb   [2 * PDIM];
__device__ float g_lb128[2 * PDIM];
__device__ float g_fac  [2 * PDIM];
__device__ __half g_uh  [(size_t)MTOT * 1024];   // u fp16
__device__ __half g_w1h [(size_t)1024 * 1024];   // W1 fp16 (scaled 2^10): [Re(Bbar); Im(Bbar)]
__device__ __half g_w2h [(size_t)1024 * 1024];   // W2 fp16: [C_re | -C_im]
__device__ __half g_Buh [(size_t)MTOT * 1024];   // GEMM1 out fp16 (scaled 2^10)
__device__ __half g_xsh [(size_t)MTOT * 1024];   // xs fp16 [re|im] (unscaled)
__device__ float g_cs_re[BSZ * NCHK * PDIM];
__device__ float g_cs_im[BSZ * NCHK * PDIM];
__device__ float g_ci_re[BSZ * NCHK * PDIM];
__device__ float g_ci_im[BSZ * NCHK * PDIM];

// ---------------- PTX helpers ----------------
__device__ __forceinline__ uint32_t smem_u32(const void* p) {
    uint32_t a;
    asm("{ .reg .u64 t; cvta.to.shared.u64 t, %1; cvt.u32.u64 %0, t; }" : "=r"(a) : "l"(p));
    return a;
}
#define CP_ASYNC16(dst, src) \
    asm volatile("cp.async.cg.shared.global [%0], [%1], 16;" :: "r"(dst), "l"(src) : "memory")
#define CP_COMMIT() asm volatile("cp.async.commit_group;" ::: "memory")
#define CP_WAIT1()  asm volatile("cp.async.wait_group 1;" ::: "memory")

__device__ __forceinline__ void ldsm4(uint32_t* r, uint32_t addr) {
    asm volatile("ldmatrix.sync.aligned.m8n8.x4.shared.b16 {%0,%1,%2,%3}, [%4];"
                 : "=r"(r[0]), "=r"(r[1]), "=r"(r[2]), "=r"(r[3]) : "r"(addr));
}
__device__ __forceinline__ void mma16816(float* d, const uint32_t* a, uint32_t b0, uint32_t b1) {
    asm volatile("mma.sync.aligned.m16n8k16.row.col.f32.f16.f16.f32 "
                 "{%0,%1,%2,%3}, {%4,%5,%6,%7}, {%8,%9}, {%0,%1,%2,%3};"
                 : "+f"(d[0]), "+f"(d[1]), "+f"(d[2]), "+f"(d[3])
                 : "r"(a[0]), "r"(a[1]), "r"(a[2]), "r"(a[3]), "r"(b0), "r"(b1));
}
#define SWZ(x) ((x) ^ (((x) >> 3) & 0x70))

// ---------------- param prep ----------------
__global__ void prep_lambda_kernel(const float* __restrict__ Lre,
                                   const float* __restrict__ Lim,
                                   const float* __restrict__ lstep)
{
    int p = blockIdx.x * blockDim.x + threadIdx.x;
    if (p >= PDIM) return;
    double lr = fmin((double)Lre[p], -1e-4);
    double li = (double)Lim[p];
    double s  = exp((double)lstep[p]);
    double er = exp(lr * s), th = li * s;
    double lbre = er * cos(th), lbim = er * sin(th);
    double den = lr * lr + li * li;
    double gre = lbre - 1.0, gim = lbim;
    g_lb[p]         = (float)lbre;
    g_lb[PDIM + p]  = (float)lbim;
    g_fac[p]        = (float)((gre * lr + gim * li) / den);
    g_fac[PDIM + p] = (float)((gim * lr - gre * li) / den);
    double er128 = exp(128.0 * lr * s), th128 = 128.0 * li * s;
    g_lb128[p]        = (float)(er128 * cos(th128));
    g_lb128[PDIM + p] = (float)(er128 * sin(th128));
}

__global__ void split_u_kernel(const float* __restrict__ u)
{
    size_t idx = (size_t)blockIdx.x * blockDim.x + threadIdx.x;
    size_t r = idx >> 8;
    int c = (int)(idx & 255) * 4;
    float4 v = *(const float4*)(u + r * 1024 + c);
    __half* o = g_uh + r * 1024;
    *(__half2*)(o + c)     = __floats2half2_rn(v.x, v.y);
    *(__half2*)(o + c + 2) = __floats2half2_rn(v.z, v.w);
}

__global__ void split_w1_kernel(const float* __restrict__ Bp)  // (P,H,2)
{
    int idx = blockIdx.x * blockDim.x + threadIdx.x;
    if (idx >= PDIM * HDIM) return;
    int p = idx >> 10, h = idx & 1023;
    float b0 = Bp[p * 2048 + h * 2 + 0];
    float b1 = Bp[p * 2048 + h * 2 + 1];
    float fr = g_fac[p], fi = g_fac[PDIM + p];
    g_w1h[(size_t)p * 1024 + h]          = __float2half_rn((fr * b0 - fi * b1) * S1_SCALE);
    g_w1h[(size_t)(PDIM + p) * 1024 + h] = __float2half_rn((fr * b1 + fi * b0) * S1_SCALE);
}

__global__ void split_w2_kernel(const float* __restrict__ Cp)  // (H,P,2)
{
    int idx = blockIdx.x * blockDim.x + threadIdx.x;
    if (idx >= HDIM * PDIM) return;
    int h = idx >> 9, p = idx & 511;
    g_w2h[(size_t)h * 1024 + p]       = __float2half_rn( Cp[h * 1024 + p * 2 + 0]);
    g_w2h[(size_t)h * 1024 + 512 + p] = __float2half_rn(-Cp[h * 1024 + p * 2 + 1]);
}

// ---------------- HMMA fp16 GEMM: C = A(Mx1024) * B(1024x1024)^T ----
// EPI=false: C is __half (direct fp16 store, values stay S1-scaled via W1).
// EPI=true : C is float, += D * u (u read as fp16).
#define STAGE_BYTES 32768
#define SMEM_SZ (3 * STAGE_BYTES)
#define NCH 16

__device__ __forceinline__ void load_chunk_async(
    const __half* __restrict__ A, const __half* __restrict__ B,
    int bm, int bn, int c, uint32_t sA, uint32_t sB, int tid)
{
    int col = c * 64;
    const char* Ag = (const char*)(A + (size_t)bm * 1024 + col);
    const char* Bg = (const char*)(B + (size_t)bn * 1024 + col);
    #pragma unroll
    for (int i = 0; i < 4; i++) {
        int idx = tid + (i << 8);
        int row = idx >> 3, ch = (idx & 7) << 4;
        CP_ASYNC16(sA + SWZ(row * 128 + ch), Ag + (size_t)row * 2048 + ch);
    }
    #pragma unroll
    for (int i = 0; i < 4; i++) {
        int idx = tid + (i << 8);
        int row = idx >> 3, ch = (idx & 7) << 4;
        CP_ASYNC16(sB + SWZ(row * 128 + ch), Bg + (size_t)row * 2048 + ch);
    }
}

template<bool EPI>
__global__ void __launch_bounds__(256, 2)
gemm_mma(const __half* __restrict__ A, const __half* __restrict__ Bm,
         void* __restrict__ Cout, const float* __restrict__ Dv,
         const __half* __restrict__ Uh)
{
    extern __shared__ char smem[];
    const uint32_t sbase = smem_u32(smem);
    const int tid = threadIdx.x;
    const int lane = tid & 31, wid = tid >> 5;
    const int wm = wid & 3, wn = wid >> 2;   // 4 x 2 warp grid: 32 rows x 64 cols
    const int bm = blockIdx.y * 128, bn = blockIdx.x * 128;

    uint32_t sA[3], sB[3];
    #pragma unroll
    for (int s = 0; s < 3; s++) { sA[s] = sbase + s * STAGE_BYTES; sB[s] = sA[s] + 16384; }

    load_chunk_async(A, Bm, bm, bn, 0, sA[0], sB[0], tid); CP_COMMIT();
    load_chunk_async(A, Bm, bm, bn, 1, sA[1], sB[1], tid); CP_COMMIT();

    float acc[2][8][4];
    #pragma unroll
    for (int i = 0; i < 2; i++)
        #pragma unroll
        for (int j = 0; j < 8; j++)
            #pragma unroll
            for (int k = 0; k < 4; k++) acc[i][j][k] = 0.0f;

    const int arow = wm * 32 + (lane & 15);
    const int brow = wn * 64 + (lane & 15);
    const int khalf = (lane >> 4) * 16;

    #pragma unroll 1
    for (int c = 0; c < NCH; c++) {
        CP_WAIT1();
        __syncthreads();
        if (c + 2 < NCH)
            load_chunk_async(A, Bm, bm, bn, c + 2, sA[(c + 2) % 3], sB[(c + 2) % 3], tid);
        CP_COMMIT();

        const uint32_t a = sA[c % 3], b = sB[c % 3];
        #pragma unroll
        for (int ks = 0; ks < 4; ks++) {
            const int kb = ks * 32 + khalf;
            uint32_t af0[4], af1[4];
            ldsm4(af0, a + SWZ(arow * 128 + kb));
            ldsm4(af1, a + SWZ((arow + 16) * 128 + kb));
            #pragma unroll
            for (int np = 0; np < 4; np++) {
                uint32_t bf[4];
                ldsm4(bf, b + SWZ((brow + np * 16) * 128 + kb));
                mma16816(acc[0][np * 2 + 0], af0, bf[0], bf[2]);
                mma16816(acc[0][np * 2 + 1], af0, bf[1], bf[3]);
                mma16816(acc[1][np * 2 + 0], af1, bf[0], bf[2]);
                mma16816(acc[1][np * 2 + 1], af1, bf[1], bf[3]);
            }
        }
    }

    // epilogue
    #pragma unroll
    for (int mt = 0; mt < 2; mt++) {
        #pragma unroll
        for (int nt = 0; nt < 8; nt++) {
            const int row = bm + wm * 32 + mt * 16 + (lane >> 2);
            const int col = bn + wn * 64 + nt * 8 + (lane & 3) * 2;
            float d0 = acc[mt][nt][0], d1 = acc[mt][nt][1];
            float d2 = acc[mt][nt][2], d3 = acc[mt][nt][3];
            if (EPI) {
                float* C = (float*)Cout;
                float2 dv = *(const float2*)(Dv + col);
                float2 u0 = __half22float2(*(const __half2*)(Uh + (size_t)row * 1024 + col));
                float2 u1 = __half22float2(*(const __half2*)(Uh + (size_t)(row + 8) * 1024 + col));
                d0 = fmaf(dv.x, u0.x, d0); d1 = fmaf(dv.y, u0.y, d1);
                d2 = fmaf(dv.x, u1.x, d2); d3 = fmaf(dv.y, u1.y, d3);
                *(float2*)(C + (size_t)row * 1024 + col)       = make_float2(d0, d1);
                *(float2*)(C + (size_t)(row + 8) * 1024 + col) = make_float2(d2, d3);
            } else {
                __half* C = (__half*)Cout;
                *(__half2*)(C + (size_t)row * 1024 + col)       = __floats2half2_rn(d0, d1);
                *(__half2*)(C + (size_t)(row + 8) * 1024 + col) = __floats2half2_rn(d2, d3);
            }
        }
    }
}

// ---------------- chunked parallel scan (all values S1-scaled until output) ----
// Each thread handles 2 adjacent p's -> half2 loads/stores.
__global__ void scan_pass1()
{
    int idx = blockIdx.x * blockDim.x + threadIdx.x;   // 65536
    int b = idx >> 13, k = (idx >> 8) & 31, q = idx & 255;
    int p0 = q * 2;
    float2 lr2 = *(const float2*)(g_lb + p0);
    float2 li2 = *(const float2*)(g_lb + PDIM + p0);
    const __half* __restrict__ bu = g_Buh + ((size_t)(b * LSEQ + k * CHUNKL)) * 1024;
    float xr0 = 0.f, xi0 = 0.f, xr1 = 0.f, xi1 = 0.f;
    #pragma unroll 4
    for (int l = 0; l < CHUNKL; l++) {
        float2 br = __half22float2(*(const __half2*)(bu + (size_t)l * 1024 + p0));
        float2 bi = __half22float2(*(const __half2*)(bu + (size_t)l * 1024 + PDIM + p0));
        float nr0 = fmaf(lr2.x, xr0, fmaf(-li2.x, xi0, br.x));
        float ni0 = fmaf(lr2.x, xi0, fmaf( li2.x, xr0, bi.x));
        float nr1 = fmaf(lr2.y, xr1, fmaf(-li2.y, xi1, br.y));
        float ni1 = fmaf(lr2.y, xi1, fmaf( li2.y, xr1, bi.y));
        xr0 = nr0; xi0 = ni0; xr1 = nr1; xi1 = ni1;
    }
    int j = ((b * NCHK + k) * PDIM) + p0;
    *(float2*)(g_cs_re + j) = make_float2(xr0, xr1);
    *(float2*)(g_cs_im + j) = make_float2(xi0, xi1);
}

__global__ void scan_pass2()
{
    int idx = blockIdx.x * blockDim.x + threadIdx.x;   // 2048
    int b = idx >> 8, q = idx & 255;
    int p0 = q * 2;
    float2 ar2 = *(const float2*)(g_lb128 + p0);
    float2 ai2 = *(const float2*)(g_lb128 + PDIM + p0);
    float cr0 = 0.f, ci0 = 0.f, cr1 = 0.f, ci1 = 0.f;
    for (int k = 0; k < NCHK; k++) {
        int j = (b * NCHK + k) * PDIM + p0;
        *(float2*)(g_ci_re + j) = make_float2(cr0, cr1);
        *(float2*)(g_ci_im + j) = make_float2(ci0, ci1);
        float2 sr = *(const float2*)(g_cs_re + j);
        float2 si = *(const float2*)(g_cs_im + j);
        float nr0 = fmaf(ar2.x, cr0, fmaf(-ai2.x, ci0, sr.x));
        float ni0 = fmaf(ar2.x, ci0, fmaf( ai2.x, cr0, si.x));
        float nr1 = fmaf(ar2.y, cr1, fmaf(-ai2.y, ci1, sr.y));
        float ni1 = fmaf(ar2.y, ci1, fmaf( ai2.y, cr1, si.y));
        cr0 = nr0; ci0 = ni0; cr1 = nr1; ci1 = ni1;
    }
}

__global__ void scan_pass3()
{
    int idx = blockIdx.x * blockDim.x + threadIdx.x;   // 65536
    int b = idx >> 13, k = (idx >> 8) & 31, q = idx & 255;
    int p0 = q * 2;
    float2 lr2 = *(const float2*)(g_lb + p0);
    float2 li2 = *(const float2*)(g_lb + PDIM + p0);
    const __half* __restrict__ bu = g_Buh + ((size_t)(b * LSEQ + k * CHUNKL)) * 1024;
    __half* __restrict__ xo = g_xsh + ((size_t)(b * LSEQ + k * CHUNKL)) * 1024;
    int j = ((b * NCHK + k) * PDIM) + p0;
    float2 cr = *(const float2*)(g_ci_re + j);
    float2 ci = *(const float2*)(g_ci_im + j);
    float xr0 = cr.x, xr1 = cr.y, xi0 = ci.x, xi1 = ci.y;
    #pragma unroll 4
    for (int l = 0; l < CHUNKL; l++) {
        float2 br = __half22float2(*(const __half2*)(bu + (size_t)l * 1024 + p0));
        float2 bi = __half22float2(*(const __half2*)(bu + (size_t)l * 1024 + PDIM + p0));
        float nr0 = fmaf(lr2.x, xr0, fmaf(-li2.x, xi0, br.x));
        float ni0 = fmaf(lr2.x, xi0, fmaf( li2.x, xr0, bi.x));
        float nr1 = fmaf(lr2.y, xr1, fmaf(-li2.y, xi1, br.y));
        float ni1 = fmaf(lr2.y, xi1, fmaf( li2.y, xr1, bi.y));
        xr0 = nr0; xi0 = ni0; xr1 = nr1; xi1 = ni1;
        __half* o = xo + (size_t)l * 1024;
        *(__half2*)(o + p0)        = __floats2half2_rn(xr0 * S1_INV, xr1 * S1_INV);
        *(__half2*)(o + PDIM + p0) = __floats2half2_rn(xi0 * S1_INV, xi1 * S1_INV);
    }
}

// ---------------- launcher ----------------
extern "C" void kernel_launch(void* const* d_in, const int* in_sizes, int n_in,
                              void* d_out, int out_size)
{
    const float* u     = (const float*)d_in[0];
    const float* Lre   = (const float*)d_in[1];
    const float* Lim   = (const float*)d_in[2];
    const float* Bp    = (const float*)d_in[3];
    const float* Cp    = (const float*)d_in[4];
    const float* Dv    = (const float*)d_in[5];
    const float* lstep = (const float*)d_in[6];
    float* out = (float*)d_out;

    void *puh, *pw1, *pw2, *pBu, *pxs;
    cudaGetSymbolAddress(&puh, g_uh);
    cudaGetSymbolAddress(&pw1, g_w1h);
    cudaGetSymbolAddress(&pw2, g_w2h);
    cudaGetSymbolAddress(&pBu, g_Buh);
    cudaGetSymbolAddress(&pxs, g_xsh);

    cudaFuncSetAttribute((const void*)gemm_mma<false>,
                         cudaFuncAttributeMaxDynamicSharedMemorySize, SMEM_SZ);
    cudaFuncSetAttribute((const void*)gemm_mma<true>,
                         cudaFuncAttributeMaxDynamicSharedMemorySize, SMEM_SZ);

    prep_lambda_kernel<<<2, 256>>>(Lre, Lim, lstep);
    split_u_kernel<<<MTOT, 256>>>(u);
    split_w1_kernel<<<(PDIM * HDIM) / 256, 256>>>(Bp);
    split_w2_kernel<<<(HDIM * PDIM) / 256, 256>>>(Cp);

    dim3 grid(1024 / 128, MTOT / 128);   // (8, 256)
    gemm_mma<false><<<grid, 256, SMEM_SZ>>>((const __half*)puh,
                                            (const __half*)pw1,
                                            pBu, nullptr, nullptr);
    scan_pass1<<<256, 256>>>();
    scan_pass2<<<8, 256>>>();
    scan_pass3<<<256, 256>>>();
    gemm_mma<true><<<grid, 256, SMEM_SZ>>>((const __half*)pxs,
                                           (const __half*)pw2,
                                           d_out, Dv, (const __half*)puh);
}

// round 7
// speedup vs baseline: 10.0626x; 1.1103x over previous
#include <cuda_runtime.h>
#include <cuda_fp16.h>
#include <math.h>
#include <stdint.h>

// ---------------- problem dims (fixed) ----------------
#define BSZ   8
#define LSEQ  4096
#define HDIM  1024
#define PDIM  512
#define MTOT  (BSZ * LSEQ)        // 32768
#define CHUNKL 128
#define NCHK  (LSEQ / CHUNKL)     // 32
#define NCHUNKS_TOT (BSZ * NCHK)  // 256

#define S1_SCALE 1024.0f          // W1 pre-scale (2^10); scan runs fully scaled
#define S1_INV   (1.0f / 1024.0f)

// ---------------- device scratch ----------------
__device__ float2 g_lbc   [PDIM];               // lambda_bar (re,im)
__device__ float2 g_lb128c[PDIM];               // lambda_bar^128
__device__ float  g_fac   [2 * PDIM];           // (lambda_bar-1)/lambda re|im
__device__ __half g_uh  [(size_t)MTOT * 1024];  // u fp16
__device__ __half g_w1h [(size_t)1024 * 1024];  // W1 fp16 scaled, rows interleaved: 2p=Re, 2p+1=Im
__device__ __half g_w2h [(size_t)1024 * 1024];  // W2 fp16, cols interleaved: 2p=C_re, 2p+1=-C_im
__device__ __half g_xsh [(size_t)MTOT * 1024];  // xs fp16 interleaved (scaled until pass3)
__device__ float2 g_cs2 [NCHUNKS_TOT * PDIM];   // chunk sums (scaled)
__device__ float2 g_ci2 [NCHUNKS_TOT * PDIM];   // chunk carry-ins (scaled)

// ---------------- PTX helpers ----------------
__device__ __forceinline__ uint32_t smem_u32(const void* p) {
    uint32_t a;
    asm("{ .reg .u64 t; cvta.to.shared.u64 t, %1; cvt.u32.u64 %0, t; }" : "=r"(a) : "l"(p));
    return a;
}
#define CP_ASYNC16(dst, src) \
    asm volatile("cp.async.cg.shared.global [%0], [%1], 16;" :: "r"(dst), "l"(src) : "memory")
#define CP_COMMIT() asm volatile("cp.async.commit_group;" ::: "memory")
#define CP_WAIT1()  asm volatile("cp.async.wait_group 1;" ::: "memory")

__device__ __forceinline__ void ldsm4(uint32_t* r, uint32_t addr) {
    asm volatile("ldmatrix.sync.aligned.m8n8.x4.shared.b16 {%0,%1,%2,%3}, [%4];"
                 : "=r"(r[0]), "=r"(r[1]), "=r"(r[2]), "=r"(r[3]) : "r"(addr));
}
__device__ __forceinline__ void mma16816(float* d, const uint32_t* a, uint32_t b0, uint32_t b1) {
    asm volatile("mma.sync.aligned.m16n8k16.row.col.f32.f16.f16.f32 "
                 "{%0,%1,%2,%3}, {%4,%5,%6,%7}, {%8,%9}, {%0,%1,%2,%3};"
                 : "+f"(d[0]), "+f"(d[1]), "+f"(d[2]), "+f"(d[3])
                 : "r"(a[0]), "r"(a[1]), "r"(a[2]), "r"(a[3]), "r"(b0), "r"(b1));
}
#define SWZ(x) ((x) ^ (((x) >> 3) & 0x70))

// ---------------- param prep ----------------
__global__ void prep_lambda_kernel(const float* __restrict__ Lre,
                                   const float* __restrict__ Lim,
                                   const float* __restrict__ lstep)
{
    int p = blockIdx.x * blockDim.x + threadIdx.x;
    if (p >= PDIM) return;
    double lr = fmin((double)Lre[p], -1e-4);
    double li = (double)Lim[p];
    double s  = exp((double)lstep[p]);
    double er = exp(lr * s), th = li * s;
    double lbre = er * cos(th), lbim = er * sin(th);
    double den = lr * lr + li * li;
    double gre = lbre - 1.0, gim = lbim;
    g_lbc[p] = make_float2((float)lbre, (float)lbim);
    g_fac[p]        = (float)((gre * lr + gim * li) / den);
    g_fac[PDIM + p] = (float)((gim * lr - gre * li) / den);
    double er128 = exp(128.0 * lr * s), th128 = 128.0 * li * s;
    g_lb128c[p] = make_float2((float)(er128 * cos(th128)), (float)(er128 * sin(th128)));
}

__global__ void split_u_kernel(const float* __restrict__ u)
{
    size_t idx = (size_t)blockIdx.x * blockDim.x + threadIdx.x;
    size_t r = idx >> 8;
    int c = (int)(idx & 255) * 4;
    float4 v = *(const float4*)(u + r * 1024 + c);
    __half* o = g_uh + r * 1024;
    *(__half2*)(o + c)     = __floats2half2_rn(v.x, v.y);
    *(__half2*)(o + c + 2) = __floats2half2_rn(v.z, v.w);
}

__global__ void split_w1_kernel(const float* __restrict__ Bp)  // (P,H,2)
{
    int idx = blockIdx.x * blockDim.x + threadIdx.x;
    if (idx >= PDIM * HDIM) return;
    int p = idx >> 10, h = idx & 1023;
    float b0 = Bp[p * 2048 + h * 2 + 0];
    float b1 = Bp[p * 2048 + h * 2 + 1];
    float fr = g_fac[p], fi = g_fac[PDIM + p];
    g_w1h[(size_t)(2 * p)     * 1024 + h] = __float2half_rn((fr * b0 - fi * b1) * S1_SCALE);
    g_w1h[(size_t)(2 * p + 1) * 1024 + h] = __float2half_rn((fr * b1 + fi * b0) * S1_SCALE);
}

__global__ void split_w2_kernel(const float* __restrict__ Cp)  // (H,P,2)
{
    int idx = blockIdx.x * blockDim.x + threadIdx.x;
    if (idx >= HDIM * PDIM) return;
    int h = idx >> 9, p = idx & 511;
    g_w2h[(size_t)h * 1024 + 2 * p]     = __float2half_rn( Cp[h * 1024 + p * 2 + 0]);
    g_w2h[(size_t)h * 1024 + 2 * p + 1] = __float2half_rn(-Cp[h * 1024 + p * 2 + 1]);
}

// ---------------- HMMA fp16 GEMM: C = A(Mx1024) * B(1024x1024)^T ----
// MODE 0 (GEMM1): epilogue runs in-CTA scan over the 128-row chunk,
//                 writes chunk-local prefix xs_local (fp16, scaled) + carry.
// MODE 1 (GEMM2): epilogue += D * u, fp32 out.
#define STAGE_BYTES 32768
#define SMEM_SZ (3 * STAGE_BYTES)
#define NCH 16

__device__ __forceinline__ void load_chunk_async(
    const __half* __restrict__ A, const __half* __restrict__ B,
    int bm, int bn, int c, uint32_t sA, uint32_t sB, int tid)
{
    int col = c * 64;
    const char* Ag = (const char*)(A + (size_t)bm * 1024 + col);
    const char* Bg = (const char*)(B + (size_t)bn * 1024 + col);
    #pragma unroll
    for (int i = 0; i < 4; i++) {
        int idx = tid + (i << 8);
        int row = idx >> 3, ch = (idx & 7) << 4;
        CP_ASYNC16(sA + SWZ(row * 128 + ch), Ag + (size_t)row * 2048 + ch);
    }
    #pragma unroll
    for (int i = 0; i < 4; i++) {
        int idx = tid + (i << 8);
        int row = idx >> 3, ch = (idx & 7) << 4;
        CP_ASYNC16(sB + SWZ(row * 128 + ch), Bg + (size_t)row * 2048 + ch);
    }
}

template<int MODE>
__global__ void __launch_bounds__(256, 2)
gemm_mma(const __half* __restrict__ A, const __half* __restrict__ Bm,
         float* __restrict__ Cout, const float* __restrict__ Dv,
         const __half* __restrict__ Uh)
{
    extern __shared__ char smem[];
    const uint32_t sbase = smem_u32(smem);
    const int tid = threadIdx.x;
    const int lane = tid & 31, wid = tid >> 5;
    const int wm = wid & 3, wn = wid >> 2;   // 4 x 2 warp grid: 32 rows x 64 cols
    const int bm = blockIdx.y * 128, bn = blockIdx.x * 128;

    uint32_t sA[3], sB[3];
    #pragma unroll
    for (int s = 0; s < 3; s++) { sA[s] = sbase + s * STAGE_BYTES; sB[s] = sA[s] + 16384; }

    load_chunk_async(A, Bm, bm, bn, 0, sA[0], sB[0], tid); CP_COMMIT();
    load_chunk_async(A, Bm, bm, bn, 1, sA[1], sB[1], tid); CP_COMMIT();

    float acc[2][8][4];
    #pragma unroll
    for (int i = 0; i < 2; i++)
        #pragma unroll
        for (int j = 0; j < 8; j++)
            #pragma unroll
            for (int k = 0; k < 4; k++) acc[i][j][k] = 0.0f;

    const int arow = wm * 32 + (lane & 15);
    const int brow = wn * 64 + (lane & 15);
    const int khalf = (lane >> 4) * 16;

    #pragma unroll 1
    for (int c = 0; c < NCH; c++) {
        CP_WAIT1();
        __syncthreads();
        if (c + 2 < NCH)
            load_chunk_async(A, Bm, bm, bn, c + 2, sA[(c + 2) % 3], sB[(c + 2) % 3], tid);
        CP_COMMIT();

        const uint32_t a = sA[c % 3], b = sB[c % 3];
        #pragma unroll
        for (int ks = 0; ks < 4; ks++) {
            const int kb = ks * 32 + khalf;
            uint32_t af0[4], af1[4];
            ldsm4(af0, a + SWZ(arow * 128 + kb));
            ldsm4(af1, a + SWZ((arow + 16) * 128 + kb));
            #pragma unroll
            for (int np = 0; np < 4; np++) {
                uint32_t bf[4];
                ldsm4(bf, b + SWZ((brow + np * 16) * 128 + kb));
                mma16816(acc[0][np * 2 + 0], af0, bf[0], bf[2]);
                mma16816(acc[0][np * 2 + 1], af0, bf[1], bf[3]);
                mma16816(acc[1][np * 2 + 0], af1, bf[0], bf[2]);
                mma16816(acc[1][np * 2 + 1], af1, bf[1], bf[3]);
            }
        }
    }

    if (MODE == 1) {
        // epilogue: += D*u, fp32 out
        #pragma unroll
        for (int mt = 0; mt < 2; mt++) {
            #pragma unroll
            for (int nt = 0; nt < 8; nt++) {
                const int row = bm + wm * 32 + mt * 16 + (lane >> 2);
                const int col = bn + wn * 64 + nt * 8 + (lane & 3) * 2;
                float d0 = acc[mt][nt][0], d1 = acc[mt][nt][1];
                float d2 = acc[mt][nt][2], d3 = acc[mt][nt][3];
                float2 dv = *(const float2*)(Dv + col);
                float2 u0 = __half22float2(*(const __half2*)(Uh + (size_t)row * 1024 + col));
                float2 u1 = __half22float2(*(const __half2*)(Uh + (size_t)(row + 8) * 1024 + col));
                d0 = fmaf(dv.x, u0.x, d0); d1 = fmaf(dv.y, u0.y, d1);
                d2 = fmaf(dv.x, u1.x, d2); d3 = fmaf(dv.y, u1.y, d3);
                *(float2*)(Cout + (size_t)row * 1024 + col)       = make_float2(d0, d1);
                *(float2*)(Cout + (size_t)(row + 8) * 1024 + col) = make_float2(d2, d3);
            }
        }
    } else {
        // epilogue: in-CTA scan over the chunk (128 l-steps x 64 complex states)
        __syncthreads();   // all ldsm done; reuse stage smem
        float* st = (float*)smem;  // [128][130]
        #pragma unroll
        for (int mt = 0; mt < 2; mt++) {
            #pragma unroll
            for (int nt = 0; nt < 8; nt++) {
                const int row = wm * 32 + mt * 16 + (lane >> 2);
                const int col = wn * 64 + nt * 8 + (lane & 3) * 2;
                *(float2*)&st[row * 130 + col]       = make_float2(acc[mt][nt][0], acc[mt][nt][1]);
                *(float2*)&st[(row + 8) * 130 + col] = make_float2(acc[mt][nt][2], acc[mt][nt][3]);
            }
        }
        __syncthreads();
        if (tid < 64) {
            const int p = (bn >> 1) + tid;
            const float2 lb = g_lbc[p];
            float xr = 0.0f, xi = 0.0f;
            __half* xout = g_xsh + (size_t)bm * 1024 + bn + 2 * tid;
            #pragma unroll 4
            for (int l = 0; l < 128; l++) {
                float2 v = *(float2*)&st[l * 130 + 2 * tid];
                float nr = fmaf(lb.x, xr, fmaf(-lb.y, xi, v.x));
                float ni = fmaf(lb.x, xi, fmaf( lb.y, xr, v.y));
                xr = nr; xi = ni;
                *(__half2*)(xout + (size_t)l * 1024) = __floats2half2_rn(xr, xi);
            }
            g_cs2[(bm >> 7) * PDIM + p] = make_float2(xr, xi);
        }
    }
}

// ---------------- cross-chunk carry scan ----------------
__global__ void scan_pass2()   // 4096 threads: (b, p)
{
    int idx = blockIdx.x * blockDim.x + threadIdx.x;
    int b = idx >> 9, p = idx & 511;
    const float2 a = g_lb128c[p];
    float2 c = make_float2(0.0f, 0.0f);
    for (int k = 0; k < NCHK; k++) {
        int j = (b * NCHK + k) * PDIM + p;
        g_ci2[j] = c;
        float2 s = g_cs2[j];
        float nr = fmaf(a.x, c.x, fmaf(-a.y, c.y, s.x));
        float ni = fmaf(a.x, c.y, fmaf( a.y, c.x, s.y));
        c = make_float2(nr, ni);
    }
}

// pass3: in-place correction  x_l = xs_local_l + lb^{l+1} * carry, then unscale.
__global__ void scan_pass3()   // 131072 threads: (chunk, p)
{
    int idx = blockIdx.x * blockDim.x + threadIdx.x;
    int chunk = idx >> 9, p = idx & 511;
    const float2 lb = g_lbc[p];
    float2 c = g_ci2[idx];
    __half* xs = g_xsh + (size_t)chunk * 128 * 1024 + 2 * p;
    #pragma unroll 4
    for (int l = 0; l < 128; l++) {
        float nr = lb.x * c.x - lb.y * c.y;
        float ni = lb.x * c.y + lb.y * c.x;
        c = make_float2(nr, ni);
        __half2* ptr = (__half2*)(xs + (size_t)l * 1024);
        float2 v = __half22float2(*ptr);
        *ptr = __floats2half2_rn((v.x + c.x) * S1_INV, (v.y + c.y) * S1_INV);
    }
}

// ---------------- launcher ----------------
extern "C" void kernel_launch(void* const* d_in, const int* in_sizes, int n_in,
                              void* d_out, int out_size)
{
    const float* u     = (const float*)d_in[0];
    const float* Lre   = (const float*)d_in[1];
    const float* Lim   = (const float*)d_in[2];
    const float* Bp    = (const float*)d_in[3];
    const float* Cp    = (const float*)d_in[4];
    const float* Dv    = (const float*)d_in[5];
    const float* lstep = (const float*)d_in[6];
    float* out = (float*)d_out;

    void *puh, *pw1, *pw2, *pxs;
    cudaGetSymbolAddress(&puh, g_uh);
    cudaGetSymbolAddress(&pw1, g_w1h);
    cudaGetSymbolAddress(&pw2, g_w2h);
    cudaGetSymbolAddress(&pxs, g_xsh);

    cudaFuncSetAttribute((const void*)gemm_mma<0>,
                         cudaFuncAttributeMaxDynamicSharedMemorySize, SMEM_SZ);
    cudaFuncSetAttribute((const void*)gemm_mma<1>,
                         cudaFuncAttributeMaxDynamicSharedMemorySize, SMEM_SZ);

    prep_lambda_kernel<<<2, 256>>>(Lre, Lim, lstep);
    split_u_kernel<<<MTOT, 256>>>(u);
    split_w1_kernel<<<(PDIM * HDIM) / 256, 256>>>(Bp);
    split_w2_kernel<<<(HDIM * PDIM) / 256, 256>>>(Cp);

    dim3 grid(1024 / 128, MTOT / 128);   // (8, 256)
    // GEMM1 + fused chunk-local scan
    gemm_mma<0><<<grid, 256, SMEM_SZ>>>((const __half*)puh, (const __half*)pw1,
                                        nullptr, nullptr, nullptr);
    scan_pass2<<<16, 256>>>();
    scan_pass3<<<512, 256>>>();
    // GEMM2: ys = xs @ W2^T + D*u
    gemm_mma<1><<<grid, 256, SMEM_SZ>>>((const __half*)pxs, (const __half*)pw2,
                                        out, Dv, (const __half*)puh);
}